// round 5
// baseline (speedup 1.0000x reference)
#include <cuda_runtime.h>
#include <cstdint>

// Problem constants (Pose_Loss: B=65536, D=154)
#define BB   65536
#define DD   154
#define N4   ((BB * DD) / 4)   // 2,523,136 — divisible by 4 exactly

// Scratch (allocation-free: __device__ globals)
__device__ float2  g_w[BB];       // (use_l, use_r) per row
__device__ double  g_acc[2];      // [0]=recon, [1]=KLD
__device__ int     g_count;

__global__ void init_kernel() {
    if (threadIdx.x == 0) { g_acc[0] = 0.0; g_acc[1] = 0.0; g_count = 0; }
}

// Pass 1: build per-row weights from int32 lr / f_pose, and count.
// NOTE: JAX with x64 disabled demotes the reference's int64 arrays to int32.
__global__ void mask_kernel(const int* __restrict__ lr,
                            const int* __restrict__ fpose) {
    int b = blockIdx.x * blockDim.x + threadIdx.x;
    if (b >= BB) return;
    int l = lr[b];
    bool valid = (fpose[b] != -1);
    bool ul = valid && (l == 0 || l == 2);
    bool ur = valid && (l == 1 || l == 2);
    g_w[b] = make_float2(ul ? 1.0f : 0.0f, ur ? 1.0f : 0.0f);

    int c = (ul ? 1 : 0) + (ur ? 1 : 0);
    // warp-level sum then one atomic per warp
    #pragma unroll
    for (int off = 16; off > 0; off >>= 1)
        c += __shfl_down_sync(0xFFFFFFFFu, c, off);
    if ((threadIdx.x & 31) == 0 && c != 0)
        atomicAdd(&g_count, c);
}

// Pass 2: main HBM-bound reduction. Flat float4 grid-stride over all 4 arrays.
__global__ void __launch_bounds__(256)
reduce_kernel(const float4* __restrict__ rl, const float4* __restrict__ rr,
              const float4* __restrict__ kl, const float4* __restrict__ kr) {
    double racc = 0.0, kacc = 0.0;

    const unsigned stride = gridDim.x * blockDim.x;
    for (unsigned i = blockIdx.x * blockDim.x + threadIdx.x; i < N4; i += stride) {
        float4 a = rl[i];
        float4 b = rr[i];
        float4 c = kl[i];
        float4 d = kr[i];

        unsigned base = i * 4u;
        unsigned row0 = base / DD;           // udiv -> mul-hi, cheap vs memory
        unsigned rem  = base - row0 * DD;

        float r, k;
        if (rem <= (unsigned)(DD - 4)) {
            // all 4 elements in the same row (~97.4% of iterations)
            float2 w = g_w[row0];
            r = w.x * ((a.x + a.y) + (a.z + a.w)) + w.y * ((b.x + b.y) + (b.z + b.w));
            k = w.x * ((c.x + c.y) + (c.z + c.w)) + w.y * ((d.x + d.y) + (d.z + d.w));
        } else {
            // float4 straddles a row boundary: resolve per element
            float ae[4] = {a.x, a.y, a.z, a.w};
            float be[4] = {b.x, b.y, b.z, b.w};
            float ce[4] = {c.x, c.y, c.z, c.w};
            float de[4] = {d.x, d.y, d.z, d.w};
            r = 0.0f; k = 0.0f;
            #pragma unroll
            for (int e = 0; e < 4; e++) {
                unsigned row = row0 + ((rem + e) >= (unsigned)DD ? 1u : 0u);
                float2 w = g_w[row];
                r += w.x * ae[e] + w.y * be[e];
                k += w.x * ce[e] + w.y * de[e];
            }
        }
        racc += (double)r;
        kacc += (double)k;
    }

    // warp reduce (doubles)
    #pragma unroll
    for (int off = 16; off > 0; off >>= 1) {
        racc += __shfl_down_sync(0xFFFFFFFFu, racc, off);
        kacc += __shfl_down_sync(0xFFFFFFFFu, kacc, off);
    }

    __shared__ double s_r[8], s_k[8];
    int wid = threadIdx.x >> 5;
    int lid = threadIdx.x & 31;
    if (lid == 0) { s_r[wid] = racc; s_k[wid] = kacc; }
    __syncthreads();

    if (wid == 0) {
        int nw = blockDim.x >> 5;
        double br = (lid < nw) ? s_r[lid] : 0.0;
        double bk = (lid < nw) ? s_k[lid] : 0.0;
        #pragma unroll
        for (int off = 4; off > 0; off >>= 1) {
            br += __shfl_down_sync(0xFFFFFFFFu, br, off);
            bk += __shfl_down_sync(0xFFFFFFFFu, bk, off);
        }
        if (lid == 0) {
            atomicAdd(&g_acc[0], br);
            atomicAdd(&g_acc[1], bk);
        }
    }
}

__global__ void finalize_kernel(float* __restrict__ out, int out_size) {
    if (threadIdx.x == 0) {
        if (out_size > 0) out[0] = (float)(g_acc[0] / 154.0);
        if (out_size > 1) out[1] = (float)g_acc[1];
        if (out_size > 2) out[2] = (float)g_count;
    }
}

extern "C" void kernel_launch(void* const* d_in, const int* in_sizes, int n_in,
                              void* d_out, int out_size) {
    const float4* rl = (const float4*)d_in[0];
    const float4* rr = (const float4*)d_in[1];
    const float4* kl = (const float4*)d_in[2];
    const float4* kr = (const float4*)d_in[3];
    const int* lr    = (const int*)d_in[4];
    const int* fpose = (const int*)d_in[5];
    float* out = (float*)d_out;

    init_kernel<<<1, 32>>>();
    mask_kernel<<<BB / 256, 256>>>(lr, fpose);
    // 148 SMs (152 on GB300); 8 blocks/SM of 256 threads
    reduce_kernel<<<1184, 256>>>(rl, rr, kl, kr);
    finalize_kernel<<<1, 32>>>(out, out_size);
}

// round 6
// speedup vs baseline: 1.0118x; 1.0118x over previous
#include <cuda_runtime.h>
#include <cstdint>

// Problem constants (Pose_Loss: B=65536, D=154)
#define BB   65536
#define DD   154
#define N4   ((BB * DD) / 4)   // 2,523,136 — divisible by 4 exactly

#define GRID_BLOCKS 1216       // 152 SMs x 8 blocks
#define BLOCK_THREADS 256

// Scratch (allocation-free device globals; zero-initialized at load,
// re-zeroed by the last block of every execution).
__device__ double        g_acc[2];   // [0]=recon, [1]=KLD
__device__ int           g_count;
__device__ unsigned int  g_done;

__device__ __forceinline__ float2 row_weights(int l, int f) {
    // lr in {0,1,2}: use_l <=> l != 1 ; use_r <=> l != 0 ; gated by f != -1
    bool valid = (f != -1);
    return make_float2((valid && l != 1) ? 1.0f : 0.0f,
                       (valid && l != 0) ? 1.0f : 0.0f);
}

__global__ void __launch_bounds__(BLOCK_THREADS)
fused_pose_loss(const float4* __restrict__ rl, const float4* __restrict__ rr,
                const float4* __restrict__ kl, const float4* __restrict__ kr,
                const int* __restrict__ lr,    const int* __restrict__ fpose,
                float* __restrict__ out, int out_size) {
    const unsigned tid    = blockIdx.x * blockDim.x + threadIdx.x;
    const unsigned stride = gridDim.x * blockDim.x;

    // ---- Phase A: count (grid-stride over rows; BB < total threads -> 1 iter) ----
    int c = 0;
    for (unsigned b = tid; b < BB; b += stride) {
        int l = lr[b];
        if (fpose[b] != -1)
            c = (l != 1 ? 1 : 0) + (l != 0 ? 1 : 0);
    }

    // ---- Phase B: main HBM-bound reduction, flat float4 grid-stride ----
    double racc = 0.0, kacc = 0.0;
    for (unsigned i = tid; i < N4; i += stride) {
        float4 a = rl[i];
        float4 b = rr[i];
        float4 cc = kl[i];
        float4 d = kr[i];

        unsigned base = i * 4u;
        unsigned row0 = base / DD;          // udiv -> mul-hi
        unsigned rem  = base - row0 * DD;

        float r, k;
        if (rem <= (unsigned)(DD - 4)) {
            // all 4 elements in the same row (~97.4%)
            float2 w = row_weights(lr[row0], fpose[row0]);
            r = w.x * ((a.x + a.y) + (a.z + a.w)) + w.y * ((b.x + b.y) + (b.z + b.w));
            k = w.x * ((cc.x + cc.y) + (cc.z + cc.w)) + w.y * ((d.x + d.y) + (d.z + d.w));
        } else {
            // float4 straddles a row boundary
            float2 w0 = row_weights(lr[row0],     fpose[row0]);
            float2 w1 = row_weights(lr[row0 + 1], fpose[row0 + 1]);
            float ae[4] = {a.x, a.y, a.z, a.w};
            float be[4] = {b.x, b.y, b.z, b.w};
            float ce[4] = {cc.x, cc.y, cc.z, cc.w};
            float de[4] = {d.x, d.y, d.z, d.w};
            r = 0.0f; k = 0.0f;
            #pragma unroll
            for (int e = 0; e < 4; e++) {
                float2 w = ((rem + e) >= (unsigned)DD) ? w1 : w0;
                r += w.x * ae[e] + w.y * be[e];
                k += w.x * ce[e] + w.y * de[e];
            }
        }
        racc += (double)r;
        kacc += (double)k;
    }

    // ---- Phase C: block reduction ----
    #pragma unroll
    for (int off = 16; off > 0; off >>= 1) {
        racc += __shfl_down_sync(0xFFFFFFFFu, racc, off);
        kacc += __shfl_down_sync(0xFFFFFFFFu, kacc, off);
        c    += __shfl_down_sync(0xFFFFFFFFu, c,    off);
    }

    __shared__ double s_r[8], s_k[8];
    __shared__ int    s_c[8];
    int wid = threadIdx.x >> 5;
    int lid = threadIdx.x & 31;
    if (lid == 0) { s_r[wid] = racc; s_k[wid] = kacc; s_c[wid] = c; }
    __syncthreads();

    if (wid == 0) {
        int nw = blockDim.x >> 5;
        double br = (lid < nw) ? s_r[lid] : 0.0;
        double bk = (lid < nw) ? s_k[lid] : 0.0;
        int    bc = (lid < nw) ? s_c[lid] : 0;
        #pragma unroll
        for (int off = 4; off > 0; off >>= 1) {
            br += __shfl_down_sync(0xFFFFFFFFu, br, off);
            bk += __shfl_down_sync(0xFFFFFFFFu, bk, off);
            bc += __shfl_down_sync(0xFFFFFFFFu, bc, off);
        }
        if (lid == 0) {
            atomicAdd(&g_acc[0], br);
            atomicAdd(&g_acc[1], bk);
            if (bc) atomicAdd(&g_count, bc);
        }
    }

    // ---- Phase D: last-block finalize + reset (single-kernel pattern) ----
    __shared__ bool is_last;
    if (threadIdx.x == 0) {
        __threadfence();                       // make this block's atomics visible
        unsigned t = atomicAdd(&g_done, 1u);
        is_last = (t == gridDim.x - 1);
    }
    __syncthreads();
    if (is_last && threadIdx.x == 0) {
        __threadfence();                       // order reads after all tickets
        double vr = g_acc[0];
        double vk = g_acc[1];
        int    vc = g_count;
        if (out_size > 0) out[0] = (float)(vr / 154.0);
        if (out_size > 1) out[1] = (float)vk;
        if (out_size > 2) out[2] = (float)vc;
        // reset for next graph replay (deterministic: every exec ends zeroed)
        g_acc[0] = 0.0;
        g_acc[1] = 0.0;
        g_count  = 0;
        __threadfence();
        g_done   = 0;
    }
}

extern "C" void kernel_launch(void* const* d_in, const int* in_sizes, int n_in,
                              void* d_out, int out_size) {
    const float4* rl = (const float4*)d_in[0];
    const float4* rr = (const float4*)d_in[1];
    const float4* kl = (const float4*)d_in[2];
    const float4* kr = (const float4*)d_in[3];
    const int* lr    = (const int*)d_in[4];
    const int* fpose = (const int*)d_in[5];
    float* out = (float*)d_out;

    fused_pose_loss<<<GRID_BLOCKS, BLOCK_THREADS>>>(rl, rr, kl, kr, lr, fpose,
                                                    out, out_size);
}

// round 7
// speedup vs baseline: 1.1132x; 1.1002x over previous
#include <cuda_runtime.h>
#include <cstdint>

// Problem constants (Pose_Loss: B=65536, D=154)
#define BB   65536
#define DD   154
#define N4   ((BB * DD) / 4)      // 2,523,136

#define BLOCK_THREADS 256
#define UNROLL 4
#define TILE  (BLOCK_THREADS * UNROLL)   // 1024 elements per tile
#define GRID_BLOCKS 1216                 // tile-stride = 1216*1024 = 1,245,184

// N4 = 2464 * TILE exactly -> no tail path needed
static_assert(N4 % TILE == 0, "tile must divide N4");

// Scratch (allocation-free device globals; zero at load, re-zeroed each exec)
__device__ double        g_acc[2];   // [0]=recon, [1]=KLD
__device__ int           g_count;
__device__ unsigned int  g_done;

__device__ __forceinline__ float2 row_weights(int l, int f) {
    // lr in {0,1,2}: use_l <=> l != 1 ; use_r <=> l != 0 ; gated by f != -1
    bool valid = (f != -1);
    return make_float2((valid && l != 1) ? 1.0f : 0.0f,
                       (valid && l != 0) ? 1.0f : 0.0f);
}

__global__ void __launch_bounds__(BLOCK_THREADS)
fused_pose_loss(const float4* __restrict__ rl, const float4* __restrict__ rr,
                const float4* __restrict__ kl, const float4* __restrict__ kr,
                const int* __restrict__ lr,    const int* __restrict__ fpose,
                float* __restrict__ out, int out_size) {
    const unsigned tid = blockIdx.x * blockDim.x + threadIdx.x;

    // ---- Phase A: per-row count (one pass over B rows) ----
    int c = 0;
    for (unsigned b = tid; b < BB; b += gridDim.x * blockDim.x) {
        int l = lr[b];
        if (fpose[b] != -1)
            c = (l != 1 ? 1 : 0) + (l != 0 ? 1 : 0);
    }

    // ---- Phase B: tiled, unrolled streaming reduction ----
    double racc = 0.0, kacc = 0.0;
    const unsigned tile_stride = gridDim.x * TILE;

    for (unsigned tbase = blockIdx.x * TILE + threadIdx.x;
         tbase < N4; tbase += tile_stride) {

        float4 A[UNROLL], Bv[UNROLL], Cv[UNROLL], Dv[UNROLL];
        unsigned row0[UNROLL], rem[UNROLL];
        int      l0[UNROLL], f0[UNROLL];

        // Batch ALL loads for 4 independent indices first (max MLP).
        #pragma unroll
        for (int j = 0; j < UNROLL; j++) {
            unsigned i = tbase + j * BLOCK_THREADS;
            A[j]  = rl[i];
            Bv[j] = rr[i];
            Cv[j] = kl[i];
            Dv[j] = kr[i];
            unsigned base = i * 4u;
            row0[j] = base / DD;            // udiv -> mul-hi
            rem[j]  = base - row0[j] * DD;
            l0[j]   = lr[row0[j]];
            f0[j]   = fpose[row0[j]];
        }

        float rt = 0.0f, kt = 0.0f;
        #pragma unroll
        for (int j = 0; j < UNROLL; j++) {
            float4 a = A[j], b = Bv[j], cc = Cv[j], d = Dv[j];
            if (rem[j] <= (unsigned)(DD - 4)) {
                // all 4 elements in the same row (~97.4%)
                float2 w = row_weights(l0[j], f0[j]);
                rt += w.x * ((a.x + a.y) + (a.z + a.w))
                    + w.y * ((b.x + b.y) + (b.z + b.w));
                kt += w.x * ((cc.x + cc.y) + (cc.z + cc.w))
                    + w.y * ((d.x + d.y) + (d.z + d.w));
            } else {
                // float4 straddles a row boundary (rare)
                float2 w0 = row_weights(l0[j], f0[j]);
                float2 w1 = row_weights(lr[row0[j] + 1], fpose[row0[j] + 1]);
                float ae[4] = {a.x, a.y, a.z, a.w};
                float be[4] = {b.x, b.y, b.z, b.w};
                float ce[4] = {cc.x, cc.y, cc.z, cc.w};
                float de[4] = {d.x, d.y, d.z, d.w};
                #pragma unroll
                for (int e = 0; e < 4; e++) {
                    float2 w = ((rem[j] + e) >= (unsigned)DD) ? w1 : w0;
                    rt += w.x * ae[e] + w.y * be[e];
                    kt += w.x * ce[e] + w.y * de[e];
                }
            }
        }
        // one double-add per tile per accumulator (short dependency chain;
        // fp32 partial is only ~32 unit-scale values -> error << 1e-3)
        racc += (double)rt;
        kacc += (double)kt;
    }

    // ---- Phase C: block reduction ----
    #pragma unroll
    for (int off = 16; off > 0; off >>= 1) {
        racc += __shfl_down_sync(0xFFFFFFFFu, racc, off);
        kacc += __shfl_down_sync(0xFFFFFFFFu, kacc, off);
        c    += __shfl_down_sync(0xFFFFFFFFu, c,    off);
    }

    __shared__ double s_r[8], s_k[8];
    __shared__ int    s_c[8];
    int wid = threadIdx.x >> 5;
    int lid = threadIdx.x & 31;
    if (lid == 0) { s_r[wid] = racc; s_k[wid] = kacc; s_c[wid] = c; }
    __syncthreads();

    if (wid == 0) {
        int nw = blockDim.x >> 5;
        double br = (lid < nw) ? s_r[lid] : 0.0;
        double bk = (lid < nw) ? s_k[lid] : 0.0;
        int    bc = (lid < nw) ? s_c[lid] : 0;
        #pragma unroll
        for (int off = 4; off > 0; off >>= 1) {
            br += __shfl_down_sync(0xFFFFFFFFu, br, off);
            bk += __shfl_down_sync(0xFFFFFFFFu, bk, off);
            bc += __shfl_down_sync(0xFFFFFFFFu, bc, off);
        }
        if (lid == 0) {
            atomicAdd(&g_acc[0], br);
            atomicAdd(&g_acc[1], bk);
            if (bc) atomicAdd(&g_count, bc);
        }
    }

    // ---- Phase D: last-block finalize + reset ----
    __shared__ bool is_last;
    if (threadIdx.x == 0) {
        __threadfence();
        unsigned t = atomicAdd(&g_done, 1u);
        is_last = (t == gridDim.x - 1);
    }
    __syncthreads();
    if (is_last && threadIdx.x == 0) {
        __threadfence();
        double vr = g_acc[0];
        double vk = g_acc[1];
        int    vc = g_count;
        if (out_size > 0) out[0] = (float)(vr / 154.0);
        if (out_size > 1) out[1] = (float)vk;
        if (out_size > 2) out[2] = (float)vc;
        g_acc[0] = 0.0;
        g_acc[1] = 0.0;
        g_count  = 0;
        __threadfence();
        g_done   = 0;
    }
}

extern "C" void kernel_launch(void* const* d_in, const int* in_sizes, int n_in,
                              void* d_out, int out_size) {
    const float4* rl = (const float4*)d_in[0];
    const float4* rr = (const float4*)d_in[1];
    const float4* kl = (const float4*)d_in[2];
    const float4* kr = (const float4*)d_in[3];
    const int* lr    = (const int*)d_in[4];
    const int* fpose = (const int*)d_in[5];
    float* out = (float*)d_out;

    fused_pose_loss<<<GRID_BLOCKS, BLOCK_THREADS>>>(rl, rr, kl, kr, lr, fpose,
                                                    out, out_size);
}